// round 1
// baseline (speedup 1.0000x reference)
#include <cuda_runtime.h>
#include <cstdint>

// Problem constants
#define TSTEPS  200
#define UDIM    128
#define BATCH   2048
#define MROWS   (BATCH * TSTEPS)      // 409600
#define GSTRIDE 384                   // xr|xz|xh concatenated
#define INSTRIDE 129                  // inputs last dim = U+1

// Scratch for precomputed input projections: 409600 x 384 fp32 = 629 MB
__device__ float g_G[157286400];      // MROWS * GSTRIDE

// ---------------- f32x2 packed helpers ----------------
__device__ __forceinline__ unsigned long long pack2(float lo, float hi) {
    unsigned long long v;
    asm("mov.b64 %0, {%1, %2};" : "=l"(v) : "f"(lo), "f"(hi));
    return v;
}
__device__ __forceinline__ void fma2(unsigned long long& d, unsigned long long a, unsigned long long b) {
    asm("fma.rn.f32x2 %0, %1, %2, %0;" : "+l"(d) : "l"(a), "l"(b));
}
__device__ __forceinline__ float2 unpack2(unsigned long long v) {
    float2 r;
    asm("mov.b64 {%0, %1}, %2;" : "=f"(r.x), "=f"(r.y) : "l"(v));
    return r;
}

// ---------------- fast activations (MUFU-based, rel err ~1e-6) ----------------
__device__ __forceinline__ float sigf(float x) {
    return __fdividef(1.0f, 1.0f + __expf(-x));
}
__device__ __forceinline__ float tanhfast(float x) {
    float e = __expf(-2.0f * fabsf(x));
    float t = __fdividef(1.0f - e, 1.0f + e);
    return copysignf(t, x);
}

// =====================================================================
// Stage 1: G[m][g*128+v] = sum_u X[m][u] * W_g[u][v] + b_g[v]
// M=409600, N=384, K=128.  Tiles: BM=64, BN=64, BK=64.
// =====================================================================
__global__ void __launch_bounds__(256) gemm_gates(
    const float* __restrict__ inp,
    const float* __restrict__ Wr, const float* __restrict__ Wz, const float* __restrict__ Wh,
    const float* __restrict__ br, const float* __restrict__ bz, const float* __restrict__ bh)
{
    __shared__ __align__(16) float As[64][68];   // [k][m], padded (16B-aligned rows)
    __shared__ __align__(16) float Bs[64][64];   // [k][n]

    const int m0 = blockIdx.x * 64;
    const int n0 = blockIdx.y * 64;              // 0..383 in steps of 64
    const int gate = n0 >> 7;                    // 0,0,1,1,2,2
    const int nc0  = n0 & 127;                   // 0 or 64
    const float* W    = (gate == 0) ? Wr : (gate == 1) ? Wz : Wh;
    const float* bias = (gate == 0) ? br : (gate == 1) ? bz : bh;

    const int tid = threadIdx.x;
    const int tx = tid & 15;                     // output col group (4 cols)
    const int ty = tid >> 4;                     // output row group (4 rows)

    unsigned long long acc[4][2] = {};           // 4 rows x (2 packed col-pairs)

    for (int k0 = 0; k0 < UDIM; k0 += 64) {
        // Load A tile transposed: As[kk][i] = X[m0+i][k0+kk]
        #pragma unroll
        for (int q = 0; q < 16; q++) {
            int idx = q * 256 + tid;
            int i = idx >> 6, kk = idx & 63;
            As[kk][i] = inp[(size_t)(m0 + i) * INSTRIDE + (k0 + kk)];
        }
        // Load B tile: Bs[kk][j] = W[k0+kk][nc0+j]
        #pragma unroll
        for (int q = 0; q < 16; q++) {
            int idx = q * 256 + tid;
            int kk = idx >> 6, j = idx & 63;
            Bs[kk][j] = W[(k0 + kk) * UDIM + nc0 + j];
        }
        __syncthreads();

        #pragma unroll
        for (int kk = 0; kk < 64; kk++) {
            float4 av = *(const float4*)&As[kk][ty * 4];
            ulonglong2 bv = *(const ulonglong2*)&Bs[kk][tx * 4];
            unsigned long long a0 = pack2(av.x, av.x);
            unsigned long long a1 = pack2(av.y, av.y);
            unsigned long long a2 = pack2(av.z, av.z);
            unsigned long long a3 = pack2(av.w, av.w);
            fma2(acc[0][0], a0, bv.x); fma2(acc[0][1], a0, bv.y);
            fma2(acc[1][0], a1, bv.x); fma2(acc[1][1], a1, bv.y);
            fma2(acc[2][0], a2, bv.x); fma2(acc[2][1], a2, bv.y);
            fma2(acc[3][0], a3, bv.x); fma2(acc[3][1], a3, bv.y);
        }
        __syncthreads();
    }

    const float4 bv4 = *(const float4*)&bias[nc0 + tx * 4];
    #pragma unroll
    for (int i = 0; i < 4; i++) {
        float2 lo = unpack2(acc[i][0]);
        float2 hi = unpack2(acc[i][1]);
        float4 v;
        v.x = lo.x + bv4.x;
        v.y = lo.y + bv4.y;
        v.z = hi.x + bv4.z;
        v.w = hi.y + bv4.w;
        *(float4*)&g_G[(size_t)(m0 + ty * 4 + i) * GSTRIDE + n0 + tx * 4] = v;
    }
}

// =====================================================================
// Stage 2: recurrence. One warp owns BR=2 batch rows for all T steps.
// CTA = 256 threads (8 warps) -> 16 rows/CTA -> grid 128 CTAs.
// Per step, each lane computes 4 output columns (c0 = lane*4):
//   acc_g[col] = sum_u h[u] * U_g[u][col]   (f32x2 packed)
// U-matrix loads are reused across the BR rows (amortizes LDG floor).
// =====================================================================
#define BR 2
#define WARPS_PER_CTA 8

__global__ void __launch_bounds__(256, 1) gru_recur(
    const float* __restrict__ inp,
    const float* __restrict__ h0,
    const float* __restrict__ Ur, const float* __restrict__ Uz, const float* __restrict__ Uh,
    float* __restrict__ out)
{
    __shared__ __align__(16) float hs[WARPS_PER_CTA][BR][UDIM];

    const int wl   = threadIdx.x >> 5;
    const int lane = threadIdx.x & 31;
    const int row0 = (blockIdx.x * WARPS_PER_CTA + wl) * BR;
    const int c0   = lane * 4;

    // init h = h0
    #pragma unroll
    for (int rr = 0; rr < BR; rr++) {
        *(float4*)&hs[wl][rr][c0] = *(const float4*)&h0[(size_t)(row0 + rr) * UDIM + c0];
    }
    __syncwarp();

    for (int t = 0; t < TSTEPS; t++) {
        unsigned long long accr[BR][2] = {};
        unsigned long long accz[BR][2] = {};
        unsigned long long acch[BR][2] = {};

        #pragma unroll 2
        for (int u = 0; u < UDIM; u += 4) {
            ulonglong2 r0 = *(const ulonglong2*)(Ur + (u + 0) * UDIM + c0);
            ulonglong2 r1 = *(const ulonglong2*)(Ur + (u + 1) * UDIM + c0);
            ulonglong2 r2 = *(const ulonglong2*)(Ur + (u + 2) * UDIM + c0);
            ulonglong2 r3 = *(const ulonglong2*)(Ur + (u + 3) * UDIM + c0);
            ulonglong2 z0 = *(const ulonglong2*)(Uz + (u + 0) * UDIM + c0);
            ulonglong2 z1 = *(const ulonglong2*)(Uz + (u + 1) * UDIM + c0);
            ulonglong2 z2 = *(const ulonglong2*)(Uz + (u + 2) * UDIM + c0);
            ulonglong2 z3 = *(const ulonglong2*)(Uz + (u + 3) * UDIM + c0);
            ulonglong2 m0v = *(const ulonglong2*)(Uh + (u + 0) * UDIM + c0);
            ulonglong2 m1v = *(const ulonglong2*)(Uh + (u + 1) * UDIM + c0);
            ulonglong2 m2v = *(const ulonglong2*)(Uh + (u + 2) * UDIM + c0);
            ulonglong2 m3v = *(const ulonglong2*)(Uh + (u + 3) * UDIM + c0);

            #pragma unroll
            for (int rr = 0; rr < BR; rr++) {
                float4 hv = *(const float4*)&hs[wl][rr][u];
                unsigned long long h0p = pack2(hv.x, hv.x);
                unsigned long long h1p = pack2(hv.y, hv.y);
                unsigned long long h2p = pack2(hv.z, hv.z);
                unsigned long long h3p = pack2(hv.w, hv.w);

                fma2(accr[rr][0], h0p, r0.x);  fma2(accr[rr][1], h0p, r0.y);
                fma2(accr[rr][0], h1p, r1.x);  fma2(accr[rr][1], h1p, r1.y);
                fma2(accr[rr][0], h2p, r2.x);  fma2(accr[rr][1], h2p, r2.y);
                fma2(accr[rr][0], h3p, r3.x);  fma2(accr[rr][1], h3p, r3.y);

                fma2(accz[rr][0], h0p, z0.x);  fma2(accz[rr][1], h0p, z0.y);
                fma2(accz[rr][0], h1p, z1.x);  fma2(accz[rr][1], h1p, z1.y);
                fma2(accz[rr][0], h2p, z2.x);  fma2(accz[rr][1], h2p, z2.y);
                fma2(accz[rr][0], h3p, z3.x);  fma2(accz[rr][1], h3p, z3.y);

                fma2(acch[rr][0], h0p, m0v.x); fma2(acch[rr][1], h0p, m0v.y);
                fma2(acch[rr][0], h1p, m1v.x); fma2(acch[rr][1], h1p, m1v.y);
                fma2(acch[rr][0], h2p, m2v.x); fma2(acch[rr][1], h2p, m2v.y);
                fma2(acch[rr][0], h3p, m3v.x); fma2(acch[rr][1], h3p, m3v.y);
            }
        }

        float4 hnew[BR];
        #pragma unroll
        for (int rr = 0; rr < BR; rr++) {
            const size_t base = (size_t)(row0 + rr) * TSTEPS + t;
            const float* g = g_G + base * GSTRIDE;
            float4 xr = *(const float4*)(g + c0);
            float4 xz = *(const float4*)(g + UDIM + c0);
            float4 xh = *(const float4*)(g + 2 * UDIM + c0);
            float a = inp[base * INSTRIDE + UDIM];
            float4 hp = *(const float4*)&hs[wl][rr][c0];

            float2 ar0 = unpack2(accr[rr][0]), ar1 = unpack2(accr[rr][1]);
            float2 az0 = unpack2(accz[rr][0]), az1 = unpack2(accz[rr][1]);
            float2 ah0 = unpack2(acch[rr][0]), ah1 = unpack2(acch[rr][1]);

            float rv0 = sigf(xr.x + ar0.x);
            float rv1 = sigf(xr.y + ar0.y);
            float rv2 = sigf(xr.z + ar1.x);
            float rv3 = sigf(xr.w + ar1.y);

            float zv0 = sigf(xz.x + az0.x);
            float zv1 = sigf(xz.y + az0.y);
            float zv2 = sigf(xz.z + az1.x);
            float zv3 = sigf(xz.w + az1.y);

            float ht0 = tanhfast(xh.x + rv0 * ah0.x);
            float ht1 = tanhfast(xh.y + rv1 * ah0.y);
            float ht2 = tanhfast(xh.z + rv2 * ah1.x);
            float ht3 = tanhfast(xh.w + rv3 * ah1.y);

            float u0 = a * zv0, u1 = a * zv1, u2 = a * zv2, u3 = a * zv3;
            hnew[rr].x = (1.0f - u0) * hp.x + u0 * ht0;
            hnew[rr].y = (1.0f - u1) * hp.y + u1 * ht1;
            hnew[rr].z = (1.0f - u2) * hp.z + u2 * ht2;
            hnew[rr].w = (1.0f - u3) * hp.w + u3 * ht3;

            *(float4*)&out[base * UDIM + c0] = hnew[rr];
        }

        __syncwarp();
        #pragma unroll
        for (int rr = 0; rr < BR; rr++) {
            *(float4*)&hs[wl][rr][c0] = hnew[rr];
        }
        __syncwarp();
    }
}

// =====================================================================
// Launch
// Inputs (metadata order): inputs, h0, W_r, U_r, b_r, W_z, U_z, b_z, W_h, U_h, b_h
// =====================================================================
extern "C" void kernel_launch(void* const* d_in, const int* in_sizes, int n_in,
                              void* d_out, int out_size)
{
    const float* inp = (const float*)d_in[0];
    const float* h0  = (const float*)d_in[1];
    const float* Wr  = (const float*)d_in[2];
    const float* Ur  = (const float*)d_in[3];
    const float* br  = (const float*)d_in[4];
    const float* Wz  = (const float*)d_in[5];
    const float* Uz  = (const float*)d_in[6];
    const float* bz  = (const float*)d_in[7];
    const float* Wh  = (const float*)d_in[8];
    const float* Uh  = (const float*)d_in[9];
    const float* bh  = (const float*)d_in[10];
    float* out = (float*)d_out;

    dim3 g1(MROWS / 64, GSTRIDE / 64);   // 6400 x 6
    gemm_gates<<<g1, 256>>>(inp, Wr, Wz, Wh, br, bz, bh);

    dim3 g2(BATCH / (WARPS_PER_CTA * BR));   // 128 CTAs
    gru_recur<<<g2, 256>>>(inp, h0, Ur, Uz, Uh, out);
}

// round 2
// speedup vs baseline: 1.0394x; 1.0394x over previous
#include <cuda_runtime.h>
#include <cstdint>

// Problem constants
#define TSTEPS   200
#define UDIM     128
#define BATCH    2048
#define MROWS    (BATCH * TSTEPS)     // 409600
#define GSTRIDE  384                  // xr|xz|xh concatenated
#define INSTRIDE 129                  // inputs last dim = U+1

// Scratch for precomputed input projections: 409600 x 384 fp32 = 629 MB
__device__ float g_G[157286400];      // MROWS * GSTRIDE

typedef unsigned long long ull;

// ---------------- f32x2 packed helpers ----------------
__device__ __forceinline__ ull pack2(float lo, float hi) {
    ull v;
    asm("mov.b64 %0, {%1, %2};" : "=l"(v) : "f"(lo), "f"(hi));
    return v;
}
__device__ __forceinline__ void fma2(ull& d, ull a, ull b) {
    asm("fma.rn.f32x2 %0, %1, %2, %0;" : "+l"(d) : "l"(a), "l"(b));
}
__device__ __forceinline__ float2 unpack2(ull v) {
    float2 r;
    asm("mov.b64 {%0, %1}, %2;" : "=f"(r.x), "=f"(r.y) : "l"(v));
    return r;
}
__device__ __forceinline__ float horiz2(ull a, ull b) {
    ull s;
    asm("add.rn.f32x2 %0, %1, %2;" : "=l"(s) : "l"(a), "l"(b));
    float2 f = unpack2(s);
    return f.x + f.y;
}

// ---------------- fast activations (MUFU-based, rel err ~1e-6) ----------------
__device__ __forceinline__ float sigf(float x) {
    return __fdividef(1.0f, 1.0f + __expf(-x));
}
__device__ __forceinline__ float tanhfast(float x) {
    float e = __expf(-2.0f * fabsf(x));
    float t = __fdividef(1.0f - e, 1.0f + e);
    return copysignf(t, x);
}

// =====================================================================
// Stage 1 (weight-stationary GEMM):
//   G[m][g*128+c] = sum_u X[m][u] * W_g[u][c] + b_g[c]
// 384 threads: thread = (gate g, column c). Holds W_g[:,c] as 64 f32x2 regs.
// X rows staged through smem (broadcast LDS), 32 rows per chunk, with
// register-prefetch double buffering of the next chunk's gmem loads.
// =====================================================================
#define GCHUNK 32
#define NCHUNK (MROWS / GCHUNK)   // 12800

__global__ void __launch_bounds__(384, 1) gemm_gates(
    const float* __restrict__ inp,
    const float* __restrict__ Wr, const float* __restrict__ Wz, const float* __restrict__ Wh,
    const float* __restrict__ br, const float* __restrict__ bz, const float* __restrict__ bh)
{
    __shared__ __align__(16) float Xs[GCHUNK][UDIM];

    const int tid  = threadIdx.x;
    const int gate = tid >> 7;
    const int c    = tid & 127;
    const float* W    = (gate == 0) ? Wr : (gate == 1) ? Wz : Wh;
    const float  bias = ((gate == 0) ? br : (gate == 1) ? bz : bh)[c];

    // Load this thread's weight column, packed over u-pairs.
    ull w[64];
    #pragma unroll
    for (int k = 0; k < 64; k++)
        w[k] = pack2(W[(2 * k) * UDIM + c], W[(2 * k + 1) * UDIM + c]);

    float stage[11];
    int ch = blockIdx.x;

    // initial prefetch
    #pragma unroll
    for (int j = 0; j < 11; j++) {
        int idx = tid + j * 384;
        if (idx < GCHUNK * UDIM)
            stage[j] = inp[(size_t)(ch * GCHUNK + (idx >> 7)) * INSTRIDE + (idx & 127)];
    }

    while (ch < NCHUNK) {
        // commit staged chunk to smem
        #pragma unroll
        for (int j = 0; j < 11; j++) {
            int idx = tid + j * 384;
            if (idx < GCHUNK * UDIM) Xs[idx >> 7][idx & 127] = stage[j];
        }
        __syncthreads();

        // prefetch next chunk into registers (latency hides under compute)
        int nch = ch + gridDim.x;
        if (nch < NCHUNK) {
            #pragma unroll
            for (int j = 0; j < 11; j++) {
                int idx = tid + j * 384;
                if (idx < GCHUNK * UDIM)
                    stage[j] = inp[(size_t)(nch * GCHUNK + (idx >> 7)) * INSTRIDE + (idx & 127)];
            }
        }

        // compute 32 dot products (2 rows at a time for ILP + weight reuse)
        float* gout = g_G + (size_t)ch * GCHUNK * GSTRIDE + gate * UDIM + c;
        #pragma unroll 1
        for (int r = 0; r < GCHUNK; r += 2) {
            const ulonglong2* hA = (const ulonglong2*)Xs[r];
            const ulonglong2* hB = (const ulonglong2*)Xs[r + 1];
            ull a0 = 0, a1 = 0, b0 = 0, b1 = 0;
            #pragma unroll
            for (int q = 0; q < 32; q++) {
                ulonglong2 xa = hA[q];
                ulonglong2 xb = hB[q];
                fma2(a0, w[2 * q],     xa.x);
                fma2(a1, w[2 * q + 1], xa.y);
                fma2(b0, w[2 * q],     xb.x);
                fma2(b1, w[2 * q + 1], xb.y);
            }
            gout[(size_t)r       * GSTRIDE] = horiz2(a0, a1) + bias;
            gout[(size_t)(r + 1) * GSTRIDE] = horiz2(b0, b1) + bias;
        }
        __syncthreads();
        ch = nch;
    }
}

// =====================================================================
// Stage 2 (weight-stationary recurrence):
// 148 CTAs x 384 threads. Thread = (gate, column c), holds U_g[:,c] in
// 64 f32x2 regs for the whole 200-step loop. CTA owns 13-14 batch rows;
// h lives in smem. Per step: matvec phase (broadcast LDS of h) then
// pointwise GRU update phase.
// =====================================================================
#define MAXR 14

__global__ void __launch_bounds__(384, 1) gru_recur(
    const float* __restrict__ inp,
    const float* __restrict__ h0,
    const float* __restrict__ Ur, const float* __restrict__ Uz, const float* __restrict__ Uh,
    float* __restrict__ out)
{
    __shared__ __align__(16) float hs[MAXR][UDIM];
    __shared__ float accs[3][MAXR][UDIM];

    const int tid  = threadIdx.x;
    const int gate = tid >> 7;
    const int c    = tid & 127;
    const float* Um = (gate == 0) ? Ur : (gate == 1) ? Uz : Uh;

    ull w[64];
    #pragma unroll
    for (int k = 0; k < 64; k++)
        w[k] = pack2(Um[(2 * k) * UDIM + c], Um[(2 * k + 1) * UDIM + c]);

    // Balanced row partition over 148 CTAs: 124 CTAs x 14 rows + 24 CTAs x 13 rows = 2048
    const int bid = blockIdx.x;
    int row0, cnt;
    if (bid < 124) { row0 = bid * 14;              cnt = 14; }
    else           { row0 = 124 * 14 + (bid - 124) * 13; cnt = 13; }

    for (int i = tid; i < cnt * UDIM; i += 384)
        hs[i >> 7][i & 127] = h0[(size_t)(row0 + (i >> 7)) * UDIM + (i & 127)];
    __syncthreads();

    for (int t = 0; t < TSTEPS; t++) {
        // ---- phase A: acc_g[r][c] = sum_u hs[r][u] * U_g[u][c] ----
        int r = 0;
        #pragma unroll 1
        for (; r + 1 < cnt; r += 2) {
            const ulonglong2* hA = (const ulonglong2*)hs[r];
            const ulonglong2* hB = (const ulonglong2*)hs[r + 1];
            ull a0 = 0, a1 = 0, b0 = 0, b1 = 0;
            #pragma unroll
            for (int q = 0; q < 32; q++) {
                ulonglong2 xa = hA[q];
                ulonglong2 xb = hB[q];
                fma2(a0, w[2 * q],     xa.x);
                fma2(a1, w[2 * q + 1], xa.y);
                fma2(b0, w[2 * q],     xb.x);
                fma2(b1, w[2 * q + 1], xb.y);
            }
            accs[gate][r][c]     = horiz2(a0, a1);
            accs[gate][r + 1][c] = horiz2(b0, b1);
        }
        if (r < cnt) {  // odd tail row
            const ulonglong2* hA = (const ulonglong2*)hs[r];
            ull a0 = 0, a1 = 0;
            #pragma unroll
            for (int q = 0; q < 32; q++) {
                ulonglong2 xa = hA[q];
                fma2(a0, w[2 * q],     xa.x);
                fma2(a1, w[2 * q + 1], xa.y);
            }
            accs[gate][r][c] = horiz2(a0, a1);
        }
        __syncthreads();

        // ---- phase B: pointwise GRU update ----
        for (int i = tid; i < cnt * UDIM; i += 384) {
            int rr = i >> 7, col = i & 127;
            size_t base = (size_t)(row0 + rr) * TSTEPS + t;
            const float* g = g_G + base * GSTRIDE;
            float xr = g[col];
            float xz = g[UDIM + col];
            float xh = g[2 * UDIM + col];
            float a  = inp[base * INSTRIDE + UDIM];
            float hp = hs[rr][col];

            float rv = sigf(xr + accs[0][rr][col]);
            float zv = sigf(xz + accs[1][rr][col]);
            float ht = tanhfast(xh + rv * accs[2][rr][col]);
            float uh = a * zv;
            float hn = (1.0f - uh) * hp + uh * ht;

            out[base * UDIM + col] = hn;
            hs[rr][col] = hn;
        }
        __syncthreads();
    }
}

// =====================================================================
// Launch
// Inputs (metadata order): inputs, h0, W_r, U_r, b_r, W_z, U_z, b_z, W_h, U_h, b_h
// =====================================================================
extern "C" void kernel_launch(void* const* d_in, const int* in_sizes, int n_in,
                              void* d_out, int out_size)
{
    const float* inp = (const float*)d_in[0];
    const float* h0  = (const float*)d_in[1];
    const float* Wr  = (const float*)d_in[2];
    const float* Ur  = (const float*)d_in[3];
    const float* br  = (const float*)d_in[4];
    const float* Wz  = (const float*)d_in[5];
    const float* Uz  = (const float*)d_in[6];
    const float* bz  = (const float*)d_in[7];
    const float* Wh  = (const float*)d_in[8];
    const float* Uh  = (const float*)d_in[9];
    const float* bh  = (const float*)d_in[10];
    float* out = (float*)d_out;

    gemm_gates<<<148, 384>>>(inp, Wr, Wz, Wh, br, bz, bh);
    gru_recur<<<148, 384>>>(inp, h0, Ur, Uz, Uh, out);
}

// round 4
// speedup vs baseline: 1.6231x; 1.5615x over previous
#include <cuda_runtime.h>
#include <cuda_bf16.h>
#include <cstdint>

// Problem constants
#define TSTEPS   200
#define UDIM     128
#define BATCH    2048
#define MROWS    (BATCH * TSTEPS)     // 409600
#define GSTRIDE  384                  // xr|xz|xh concatenated
#define INSTRIDE 129                  // inputs last dim = U+1

// Scratch for precomputed input projections: 409600 x 384 fp32 = 629 MB
__device__ float g_G[157286400];      // MROWS * GSTRIDE

typedef unsigned long long ull;

// ---------------- f32x2 packed helpers ----------------
__device__ __forceinline__ ull pack2(float lo, float hi) {
    ull v;
    asm("mov.b64 %0, {%1, %2};" : "=l"(v) : "f"(lo), "f"(hi));
    return v;
}
__device__ __forceinline__ void fma2(ull& d, ull a, ull b) {
    asm("fma.rn.f32x2 %0, %1, %2, %0;" : "+l"(d) : "l"(a), "l"(b));
}
__device__ __forceinline__ float2 unpack2(ull v) {
    float2 r;
    asm("mov.b64 {%0, %1}, %2;" : "=f"(r.x), "=f"(r.y) : "l"(v));
    return r;
}
__device__ __forceinline__ float horiz2(ull a, ull b) {
    ull s;
    asm("add.rn.f32x2 %0, %1, %2;" : "=l"(s) : "l"(a), "l"(b));
    float2 f = unpack2(s);
    return f.x + f.y;
}

// ---------------- fast activations ----------------
__device__ __forceinline__ float sigf(float x) {
    return __fdividef(1.0f, 1.0f + __expf(-x));
}
__device__ __forceinline__ float tanhfast(float x) {
    float e = __expf(-2.0f * fabsf(x));
    float t = __fdividef(1.0f - e, 1.0f + e);
    return copysignf(t, x);
}

// ---------------- cp.async helpers ----------------
__device__ __forceinline__ void cpa16(uint32_t saddr, const void* g) {
    asm volatile("cp.async.ca.shared.global [%0], [%1], 16;" :: "r"(saddr), "l"(g));
}
__device__ __forceinline__ void cpa4(uint32_t saddr, const void* g) {
    asm volatile("cp.async.ca.shared.global [%0], [%1], 4;" :: "r"(saddr), "l"(g));
}
__device__ __forceinline__ void cpa_commit() { asm volatile("cp.async.commit_group;"); }
__device__ __forceinline__ void cpa_wait0()  { asm volatile("cp.async.wait_group 0;"); }

// ---------------- mma.sync helpers ----------------
__device__ __forceinline__ void mma16816(float* c, const uint32_t* a, const uint32_t* b) {
    asm volatile(
        "mma.sync.aligned.m16n8k16.row.col.f32.bf16.bf16.f32 "
        "{%0,%1,%2,%3}, {%4,%5,%6,%7}, {%8,%9}, {%0,%1,%2,%3};"
        : "+f"(c[0]), "+f"(c[1]), "+f"(c[2]), "+f"(c[3])
        : "r"(a[0]), "r"(a[1]), "r"(a[2]), "r"(a[3]), "r"(b[0]), "r"(b[1]));
}
__device__ __forceinline__ void lds128(uint32_t* r, uint32_t addr) {
    asm volatile("ld.shared.v4.u32 {%0,%1,%2,%3}, [%4];"
        : "=r"(r[0]), "=r"(r[1]), "=r"(r[2]), "=r"(r[3]) : "r"(addr));
}
__device__ __forceinline__ void lds64(uint32_t* r, uint32_t addr) {
    asm volatile("ld.shared.v2.u32 {%0,%1}, [%2];"
        : "=r"(r[0]), "=r"(r[1]) : "r"(addr));
}
__device__ __forceinline__ void sts32(uint32_t addr, uint32_t v) {
    asm volatile("st.shared.u32 [%0], %1;" :: "r"(addr), "r"(v));
}
// Split packed pair (x0, x1) into bf16x2 hi and lo parts. lo half of reg = x0.
__device__ __forceinline__ void split2(float x0, float x1, uint32_t& hi, uint32_t& lo) {
    asm("cvt.rn.bf16x2.f32 %0, %1, %2;" : "=r"(hi) : "f"(x1), "f"(x0));
    float h0 = __uint_as_float(hi << 16);
    float h1 = __uint_as_float(hi & 0xFFFF0000u);
    float l0 = x0 - h0;
    float l1 = x1 - h1;
    asm("cvt.rn.bf16x2.f32 %0, %1, %2;" : "=r"(lo) : "f"(l1), "f"(l0));
}

// =====================================================================
// Stage 1: G[m][n] = X[m][:] . Wcat[:][n] + bias, via mma.sync bf16
// 3-pass split. M-tile 128, N-tile 128 (one gate), K=128.
// smem holds tiles pre-arranged in m16n8k16 fragment order:
//   A frag blocks: [mfrag(8)][kstep(8)] x 32 lanes x 16B  (kstep-XOR swizzled)
//   B frag blocks: [nfrag(16)][kstep(8)] x 32 lanes x 8B
// =====================================================================
#define OFF_AHI  0
#define OFF_ALO  32768
#define OFF_BHI  65536
#define OFF_BLO  98304
#define OFF_BIAS 131072
#define GM_SMEM  131584

__global__ void __launch_bounds__(256, 1) gemm_tc(
    const float* __restrict__ inp,
    const float* __restrict__ Wr, const float* __restrict__ Wz, const float* __restrict__ Wh,
    const float* __restrict__ br, const float* __restrict__ bz, const float* __restrict__ bh)
{
    extern __shared__ __align__(16) char smem[];
    const uint32_t sb = (uint32_t)__cvta_generic_to_shared(smem);
    float* bias_s = (float*)(smem + OFF_BIAS);

    const int tid  = threadIdx.x;
    const int wid  = tid >> 5;
    const int lane = tid & 31;
    const int wm   = wid >> 1;            // 0..3 : warp m-block (32 rows)
    const int wn   = wid & 1;             // 0..1 : warp n-block (64 cols)

    const int bid   = blockIdx.x;
    const int nblk  = bid % 3;            // gate index (fixed per CTA)
    const int start = bid / 3;
    const int mstride = (nblk == 0) ? 50 : 49;

    const float* Wg   = (nblk == 0) ? Wr : (nblk == 1) ? Wz : Wh;
    const float* bsrc = (nblk == 0) ? br : (nblk == 1) ? bz : bh;

    // ---- load + split W into B-fragment layout (once per CTA) ----
    {
        const int rbase = tid >> 6;       // 0..3
        const int kp    = tid & 63;       // k-pair 0..63
        const int ks  = kp >> 3;
        const int chi = (kp >> 2) & 1;
        #pragma unroll 4
        for (int j = 0; j < 32; j++) {
            int n = j * 4 + rbase;
            float w0 = Wg[(2 * kp) * UDIM + n];
            float w1 = Wg[(2 * kp + 1) * UDIM + n];
            uint32_t hi, lo;
            split2(w0, w1, hi, lo);
            int nfrag = n >> 3, nn = n & 7;
            uint32_t off = (uint32_t)((nfrag * 8 + ks) << 8) + ((nn * 4 + (kp & 3)) << 3) + (chi << 2);
            sts32(sb + OFF_BHI + off, hi);
            sts32(sb + OFF_BLO + off, lo);
        }
        if (tid < 128) bias_s[tid] = bsrc[tid];
    }
    __syncthreads();

    const int eg  = lane >> 2;            // epilogue row-in-frag
    const int et2 = (lane & 3) * 2;       // epilogue col-pair

    for (int mt = start; mt < 3200; mt += mstride) {
        const size_t m0 = (size_t)mt * 128;

        // ---- load + split X into A-fragment layout ----
        {
            const int rbase = tid >> 6;
            const int kp    = tid & 63;
            const int ks  = kp >> 3;
            const int t   = kp & 3;
            const int chi = (kp >> 2) & 1;
            #pragma unroll 4
            for (int j = 0; j < 32; j++) {
                int m = j * 4 + rbase;
                const float* p = inp + (m0 + m) * INSTRIDE + 2 * kp;
                float x0 = p[0];
                float x1 = p[1];
                uint32_t hi, lo;
                split2(x0, x1, hi, lo);
                int mfrag = m >> 4, r = m & 15, g = r & 7, rh = r >> 3;
                int lane_sw = (g * 4 + t) ^ ((ks & 3) << 1);
                uint32_t off = (uint32_t)((mfrag * 8 + ks) << 9) + (lane_sw << 4) + ((chi * 2 + rh) << 2);
                sts32(sb + OFF_AHI + off, hi);
                sts32(sb + OFF_ALO + off, lo);
            }
        }
        __syncthreads();

        // ---- mma mainloop ----
        float acc[2][8][4];
        #pragma unroll
        for (int mf = 0; mf < 2; mf++)
            #pragma unroll
            for (int nf = 0; nf < 8; nf++)
                #pragma unroll
                for (int q = 0; q < 4; q++) acc[mf][nf][q] = 0.0f;

        #pragma unroll 2
        for (int ks = 0; ks < 8; ks++) {
            const uint32_t asw = (uint32_t)((lane ^ ((ks & 3) << 1)) << 4);
            uint32_t Ahi[2][4], Alo[2][4];
            #pragma unroll
            for (int mf = 0; mf < 2; mf++) {
                uint32_t blk = (uint32_t)(((wm * 2 + mf) * 8 + ks) << 9) + asw;
                lds128(Ahi[mf], sb + OFF_AHI + blk);
                lds128(Alo[mf], sb + OFF_ALO + blk);
            }
            uint32_t Bhi[8][2], Blo[8][2];
            #pragma unroll
            for (int nf = 0; nf < 8; nf++) {
                uint32_t blk = (uint32_t)(((wn * 8 + nf) * 8 + ks) << 8) + (lane << 3);
                lds64(Bhi[nf], sb + OFF_BHI + blk);
                lds64(Blo[nf], sb + OFF_BLO + blk);
            }
            #pragma unroll
            for (int mf = 0; mf < 2; mf++)
                #pragma unroll
                for (int nf = 0; nf < 8; nf++) {
                    mma16816(acc[mf][nf], Ahi[mf], Bhi[nf]);
                    mma16816(acc[mf][nf], Ahi[mf], Blo[nf]);
                    mma16816(acc[mf][nf], Alo[mf], Bhi[nf]);
                }
        }

        // ---- epilogue: direct STG.64 (32B-sector coalesced) ----
        #pragma unroll
        for (int mf = 0; mf < 2; mf++) {
            size_t row = m0 + wm * 32 + mf * 16 + eg;
            #pragma unroll
            for (int nf = 0; nf < 8; nf++) {
                int coll = wn * 64 + nf * 8 + et2;
                float b0 = bias_s[coll], b1 = bias_s[coll + 1];
                float* gp = g_G + row * GSTRIDE + nblk * 128 + coll;
                float2 v0 = make_float2(acc[mf][nf][0] + b0, acc[mf][nf][1] + b1);
                float2 v1 = make_float2(acc[mf][nf][2] + b0, acc[mf][nf][3] + b1);
                *(float2*)gp = v0;
                *(float2*)(gp + 8 * GSTRIDE) = v1;
            }
        }
        __syncthreads();   // protect frag smem before next tile's stores
    }
}

// =====================================================================
// Stage 2: weight-stationary recurrence with cp.async phase-B prefetch.
// =====================================================================
#define MAXR 14

__global__ void __launch_bounds__(384, 1) gru_recur(
    const float* __restrict__ inp,
    const float* __restrict__ h0,
    const float* __restrict__ Ur, const float* __restrict__ Uz, const float* __restrict__ Uh,
    float* __restrict__ out)
{
    __shared__ __align__(16) float hs[MAXR][UDIM];
    __shared__ float accs[3][MAXR][UDIM];
    __shared__ __align__(16) float gxs[MAXR][GSTRIDE];
    __shared__ float as_s[MAXR];

    const int tid  = threadIdx.x;
    const int gate = tid >> 7;
    const int c    = tid & 127;
    const float* Um = (gate == 0) ? Ur : (gate == 1) ? Uz : Uh;

    ull w[64];
    #pragma unroll
    for (int k = 0; k < 64; k++)
        w[k] = pack2(Um[(2 * k) * UDIM + c], Um[(2 * k + 1) * UDIM + c]);

    // Balanced row partition over 148 CTAs
    const int bid = blockIdx.x;
    int row0, cnt;
    if (bid < 124) { row0 = bid * 14;                    cnt = 14; }
    else           { row0 = 124 * 14 + (bid - 124) * 13; cnt = 13; }

    for (int i = tid; i < cnt * UDIM; i += 384)
        hs[i >> 7][i & 127] = h0[(size_t)(row0 + (i >> 7)) * UDIM + (i & 127)];
    __syncthreads();

    const uint32_t gxs_base = (uint32_t)__cvta_generic_to_shared(&gxs[0][0]);
    const uint32_t as_base  = (uint32_t)__cvta_generic_to_shared(&as_s[0]);

    for (int t = 0; t < TSTEPS; t++) {
        // ---- issue cp.async prefetch of this step's phase-B operands ----
        {
            int nchunks = cnt * 96;   // 16B chunks of g_G rows
            for (int i = tid; i < nchunks; i += 384) {
                int rr = i / 96, q = i - rr * 96;
                size_t base = (size_t)(row0 + rr) * TSTEPS + t;
                cpa16(gxs_base + (uint32_t)(rr * GSTRIDE + q * 4) * 4,
                      g_G + base * GSTRIDE + q * 4);
            }
            if (tid < cnt) {
                size_t base = (size_t)(row0 + tid) * TSTEPS + t;
                cpa4(as_base + tid * 4, inp + base * INSTRIDE + UDIM);
            }
            cpa_commit();
        }

        // ---- phase A: acc_g[r][c] = sum_u hs[r][u] * U_g[u][c] ----
        int r = 0;
        #pragma unroll 1
        for (; r + 1 < cnt; r += 2) {
            const ulonglong2* hA = (const ulonglong2*)hs[r];
            const ulonglong2* hB = (const ulonglong2*)hs[r + 1];
            ull a0 = 0, a1 = 0, b0 = 0, b1 = 0;
            #pragma unroll
            for (int q = 0; q < 32; q++) {
                ulonglong2 xa = hA[q];
                ulonglong2 xb = hB[q];
                fma2(a0, w[2 * q],     xa.x);
                fma2(a1, w[2 * q + 1], xa.y);
                fma2(b0, w[2 * q],     xb.x);
                fma2(b1, w[2 * q + 1], xb.y);
            }
            accs[gate][r][c]     = horiz2(a0, a1);
            accs[gate][r + 1][c] = horiz2(b0, b1);
        }
        if (r < cnt) {
            const ulonglong2* hA = (const ulonglong2*)hs[r];
            ull a0 = 0, a1 = 0;
            #pragma unroll
            for (int q = 0; q < 32; q++) {
                ulonglong2 xa = hA[q];
                fma2(a0, w[2 * q],     xa.x);
                fma2(a1, w[2 * q + 1], xa.y);
            }
            accs[gate][r][c] = horiz2(a0, a1);
        }
        cpa_wait0();
        __syncthreads();

        // ---- phase B: pointwise GRU update (operands in smem) ----
        for (int i = tid; i < cnt * UDIM; i += 384) {
            int rr = i >> 7, col = i & 127;
            size_t base = (size_t)(row0 + rr) * TSTEPS + t;
            float xr = gxs[rr][col];
            float xz = gxs[rr][UDIM + col];
            float xh = gxs[rr][2 * UDIM + col];
            float a  = as_s[rr];
            float hp = hs[rr][col];

            float rv = sigf(xr + accs[0][rr][col]);
            float zv = sigf(xz + accs[1][rr][col]);
            float ht = tanhfast(xh + rv * accs[2][rr][col]);
            float uh = a * zv;
            float hn = (1.0f - uh) * hp + uh * ht;

            out[base * UDIM + col] = hn;
            hs[rr][col] = hn;
        }
        __syncthreads();
    }
}

// =====================================================================
// Launch
// Inputs (metadata order): inputs, h0, W_r, U_r, b_r, W_z, U_z, b_z, W_h, U_h, b_h
// =====================================================================
extern "C" void kernel_launch(void* const* d_in, const int* in_sizes, int n_in,
                              void* d_out, int out_size)
{
    const float* inp = (const float*)d_in[0];
    const float* h0  = (const float*)d_in[1];
    const float* Wr  = (const float*)d_in[2];
    const float* Ur  = (const float*)d_in[3];
    const float* br  = (const float*)d_in[4];
    const float* Wz  = (const float*)d_in[5];
    const float* Uz  = (const float*)d_in[6];
    const float* bz  = (const float*)d_in[7];
    const float* Wh  = (const float*)d_in[8];
    const float* Uh  = (const float*)d_in[9];
    const float* bh  = (const float*)d_in[10];
    float* out = (float*)d_out;

    cudaFuncSetAttribute(gemm_tc, cudaFuncAttributeMaxDynamicSharedMemorySize, GM_SMEM);

    gemm_tc<<<148, 256, GM_SMEM>>>(inp, Wr, Wz, Wh, br, bz, bh);
    gru_recur<<<148, 384>>>(inp, h0, Ur, Uz, Uh, out);
}

// round 5
// speedup vs baseline: 2.7707x; 1.7071x over previous
#include <cuda_runtime.h>
#include <cuda_bf16.h>
#include <cstdint>

// Problem constants
#define TSTEPS   200
#define UDIM     128
#define BATCH    2048
#define MROWS    (BATCH * TSTEPS)     // 409600
#define GSTRIDE  384                  // xr|xz|xh concatenated
#define INSTRIDE 129                  // inputs last dim = U+1

// Scratch for precomputed input projections: 409600 x 384 fp32 = 629 MB
__device__ float g_G[157286400];      // MROWS * GSTRIDE

typedef unsigned long long ull;

// ---------------- fast activations ----------------
__device__ __forceinline__ float sigf(float x) {
    return __fdividef(1.0f, 1.0f + __expf(-x));
}
__device__ __forceinline__ float tanhfast(float x) {
    float e = __expf(-2.0f * fabsf(x));
    float t = __fdividef(1.0f - e, 1.0f + e);
    return copysignf(t, x);
}

// ---------------- cp.async helpers ----------------
__device__ __forceinline__ void cpa16(uint32_t saddr, const void* g) {
    asm volatile("cp.async.ca.shared.global [%0], [%1], 16;" :: "r"(saddr), "l"(g));
}
__device__ __forceinline__ void cpa4(uint32_t saddr, const void* g) {
    asm volatile("cp.async.ca.shared.global [%0], [%1], 4;" :: "r"(saddr), "l"(g));
}
__device__ __forceinline__ void cpa_commit() { asm volatile("cp.async.commit_group;"); }
__device__ __forceinline__ void cpa_wait0()  { asm volatile("cp.async.wait_group 0;"); }

// ---------------- mma.sync helpers ----------------
__device__ __forceinline__ void mma16816(float* c, const uint32_t* a, const uint32_t* b) {
    asm volatile(
        "mma.sync.aligned.m16n8k16.row.col.f32.bf16.bf16.f32 "
        "{%0,%1,%2,%3}, {%4,%5,%6,%7}, {%8,%9}, {%0,%1,%2,%3};"
        : "+f"(c[0]), "+f"(c[1]), "+f"(c[2]), "+f"(c[3])
        : "r"(a[0]), "r"(a[1]), "r"(a[2]), "r"(a[3]), "r"(b[0]), "r"(b[1]));
}
__device__ __forceinline__ void lds128(uint32_t* r, uint32_t addr) {
    asm volatile("ld.shared.v4.u32 {%0,%1,%2,%3}, [%4];"
        : "=r"(r[0]), "=r"(r[1]), "=r"(r[2]), "=r"(r[3]) : "r"(addr));
}
__device__ __forceinline__ void lds64(uint32_t* r, uint32_t addr) {
    asm volatile("ld.shared.v2.u32 {%0,%1}, [%2];"
        : "=r"(r[0]), "=r"(r[1]) : "r"(addr));
}
__device__ __forceinline__ void sts32(uint32_t addr, uint32_t v) {
    asm volatile("st.shared.u32 [%0], %1;" :: "r"(addr), "r"(v));
}
__device__ __forceinline__ void sts64f(uint32_t addr, float x, float y) {
    asm volatile("st.shared.v2.f32 [%0], {%1,%2};" :: "r"(addr), "f"(x), "f"(y));
}
// Split packed pair (x0, x1) into bf16x2 hi and lo parts. lo half of reg = x0.
__device__ __forceinline__ void split2(float x0, float x1, uint32_t& hi, uint32_t& lo) {
    asm("cvt.rn.bf16x2.f32 %0, %1, %2;" : "=r"(hi) : "f"(x1), "f"(x0));
    float h0 = __uint_as_float(hi << 16);
    float h1 = __uint_as_float(hi & 0xFFFF0000u);
    float l0 = x0 - h0;
    float l1 = x1 - h1;
    asm("cvt.rn.bf16x2.f32 %0, %1, %2;" : "=r"(lo) : "f"(l1), "f"(l0));
}

// =====================================================================
// Stage 1: G[m][n] = X[m][:] . Wcat[:][n] + bias, via mma.sync bf16
// 3-pass split. M-tile 128, N-tile 128 (one gate), K=128. (unchanged)
// =====================================================================
#define OFF_AHI  0
#define OFF_ALO  32768
#define OFF_BHI  65536
#define OFF_BLO  98304
#define OFF_BIAS 131072
#define GM_SMEM  131584

__global__ void __launch_bounds__(256, 1) gemm_tc(
    const float* __restrict__ inp,
    const float* __restrict__ Wr, const float* __restrict__ Wz, const float* __restrict__ Wh,
    const float* __restrict__ br, const float* __restrict__ bz, const float* __restrict__ bh)
{
    extern __shared__ __align__(16) char smem[];
    const uint32_t sb = (uint32_t)__cvta_generic_to_shared(smem);
    float* bias_s = (float*)(smem + OFF_BIAS);

    const int tid  = threadIdx.x;
    const int wid  = tid >> 5;
    const int lane = tid & 31;
    const int wm   = wid >> 1;
    const int wn   = wid & 1;

    const int bid   = blockIdx.x;
    const int nblk  = bid % 3;
    const int start = bid / 3;
    const int mstride = (nblk == 0) ? 50 : 49;

    const float* Wg   = (nblk == 0) ? Wr : (nblk == 1) ? Wz : Wh;
    const float* bsrc = (nblk == 0) ? br : (nblk == 1) ? bz : bh;

    {
        const int rbase = tid >> 6;
        const int kp    = tid & 63;
        const int ks  = kp >> 3;
        const int chi = (kp >> 2) & 1;
        #pragma unroll 4
        for (int j = 0; j < 32; j++) {
            int n = j * 4 + rbase;
            float w0 = Wg[(2 * kp) * UDIM + n];
            float w1 = Wg[(2 * kp + 1) * UDIM + n];
            uint32_t hi, lo;
            split2(w0, w1, hi, lo);
            int nfrag = n >> 3, nn = n & 7;
            uint32_t off = (uint32_t)((nfrag * 8 + ks) << 8) + ((nn * 4 + (kp & 3)) << 3) + (chi << 2);
            sts32(sb + OFF_BHI + off, hi);
            sts32(sb + OFF_BLO + off, lo);
        }
        if (tid < 128) bias_s[tid] = bsrc[tid];
    }
    __syncthreads();

    const int eg  = lane >> 2;
    const int et2 = (lane & 3) * 2;

    for (int mt = start; mt < 3200; mt += mstride) {
        const size_t m0 = (size_t)mt * 128;

        {
            const int rbase = tid >> 6;
            const int kp    = tid & 63;
            const int ks  = kp >> 3;
            const int t   = kp & 3;
            const int chi = (kp >> 2) & 1;
            #pragma unroll 4
            for (int j = 0; j < 32; j++) {
                int m = j * 4 + rbase;
                const float* p = inp + (m0 + m) * INSTRIDE + 2 * kp;
                float x0 = p[0];
                float x1 = p[1];
                uint32_t hi, lo;
                split2(x0, x1, hi, lo);
                int mfrag = m >> 4, r = m & 15, g = r & 7, rh = r >> 3;
                int lane_sw = (g * 4 + t) ^ ((ks & 3) << 1);
                uint32_t off = (uint32_t)((mfrag * 8 + ks) << 9) + (lane_sw << 4) + ((chi * 2 + rh) << 2);
                sts32(sb + OFF_AHI + off, hi);
                sts32(sb + OFF_ALO + off, lo);
            }
        }
        __syncthreads();

        float acc[2][8][4];
        #pragma unroll
        for (int mf = 0; mf < 2; mf++)
            #pragma unroll
            for (int nf = 0; nf < 8; nf++)
                #pragma unroll
                for (int q = 0; q < 4; q++) acc[mf][nf][q] = 0.0f;

        #pragma unroll 2
        for (int ks = 0; ks < 8; ks++) {
            const uint32_t asw = (uint32_t)((lane ^ ((ks & 3) << 1)) << 4);
            uint32_t Ahi[2][4], Alo[2][4];
            #pragma unroll
            for (int mf = 0; mf < 2; mf++) {
                uint32_t blk = (uint32_t)(((wm * 2 + mf) * 8 + ks) << 9) + asw;
                lds128(Ahi[mf], sb + OFF_AHI + blk);
                lds128(Alo[mf], sb + OFF_ALO + blk);
            }
            uint32_t Bhi[8][2], Blo[8][2];
            #pragma unroll
            for (int nf = 0; nf < 8; nf++) {
                uint32_t blk = (uint32_t)(((wn * 8 + nf) * 8 + ks) << 8) + (lane << 3);
                lds64(Bhi[nf], sb + OFF_BHI + blk);
                lds64(Blo[nf], sb + OFF_BLO + blk);
            }
            #pragma unroll
            for (int mf = 0; mf < 2; mf++)
                #pragma unroll
                for (int nf = 0; nf < 8; nf++) {
                    mma16816(acc[mf][nf], Ahi[mf], Bhi[nf]);
                    mma16816(acc[mf][nf], Ahi[mf], Blo[nf]);
                    mma16816(acc[mf][nf], Alo[mf], Bhi[nf]);
                }
        }

        #pragma unroll
        for (int mf = 0; mf < 2; mf++) {
            size_t row = m0 + wm * 32 + mf * 16 + eg;
            #pragma unroll
            for (int nf = 0; nf < 8; nf++) {
                int coll = wn * 64 + nf * 8 + et2;
                float b0 = bias_s[coll], b1 = bias_s[coll + 1];
                float* gp = g_G + row * GSTRIDE + nblk * 128 + coll;
                float2 v0 = make_float2(acc[mf][nf][0] + b0, acc[mf][nf][1] + b1);
                float2 v1 = make_float2(acc[mf][nf][2] + b0, acc[mf][nf][3] + b1);
                *(float2*)gp = v0;
                *(float2*)(gp + 8 * GSTRIDE) = v1;
            }
        }
        __syncthreads();
    }
}

// =====================================================================
// Stage 2: tensor-core recurrence.
// Per CTA per step: [16 x 128] h-matrix @ [128 x 384] U-cat via
// m16n8k16 bf16 3-pass split. 12 warps, warp w owns 32 cols of the
// 384-col concat (gate = w>>2). U-hi frags resident in registers,
// U-lo frags in smem. h (A operand) rebuilt in frag-order smem each
// step by the pointwise phase.
// =====================================================================
#define OFF2_BLO  0                    // 48 nfrags x 8 ks x 256B = 98304
#define OFF2_AFH  98304                // 8 ks x 32 lanes x 16B = 4096
#define OFF2_AFL  102400               // 4096
#define OFF2_ACC  106496               // 3*16*132*4 = 25344
#define OFF2_HS   131840               // 16*128*4 = 8192
#define OFF2_GXS  140032               // 14*384*4 = 21504
#define OFF2_AS   161536               // 64
#define SMEM2     161600

__device__ __forceinline__ uint32_t afrag_off(int r, int u2) {
    int ks   = u2 >> 4;
    int lane = ((r & 7) << 2) | ((u2 >> 1) & 3);
    int reg  = (r >> 3) | (((u2 >> 3) & 1) << 1);
    return (uint32_t)(ks * 512 + lane * 16 + reg * 4);
}

__global__ void __launch_bounds__(384, 1) gru_recur(
    const float* __restrict__ inp,
    const float* __restrict__ h0,
    const float* __restrict__ Ur, const float* __restrict__ Uz, const float* __restrict__ Uh,
    float* __restrict__ out)
{
    extern __shared__ __align__(16) char smem2[];
    const uint32_t sb = (uint32_t)__cvta_generic_to_shared(smem2);
    float* hs   = (float*)(smem2 + OFF2_HS);
    float* gxs  = (float*)(smem2 + OFF2_GXS);
    float* as_s = (float*)(smem2 + OFF2_AS);
    float* accs = (float*)(smem2 + OFF2_ACC);

    const int tid  = threadIdx.x;
    const int wid  = tid >> 5;
    const int lane = tid & 31;

    // Balanced row partition over 148 CTAs: 124x14 + 24x13 = 2048
    const int bid = blockIdx.x;
    int row0, cnt;
    if (bid < 124) { row0 = bid * 14;                    cnt = 14; }
    else           { row0 = 124 * 14 + (bid - 124) * 13; cnt = 13; }

    // zero A-frag regions (covers padded rows cnt..15 forever)
    for (int i = tid; i < 1024; i += 384) {
        ((uint32_t*)(smem2 + OFF2_AFH))[i] = 0;
        ((uint32_t*)(smem2 + OFF2_AFL))[i] = 0;
    }
    // load h0
    for (int i = tid; i < cnt * UDIM; i += 384)
        hs[i] = h0[(size_t)row0 * UDIM + i];

    // ---- build B (U-cat) hi parts in frag layout ----
    for (int idx = tid; idx < 384 * 64; idx += 384) {
        int n = idx >> 6, kp = idx & 63;
        int g = n >> 7, col = n & 127;
        const float* Ug = (g == 0) ? Ur : (g == 1) ? Uz : Uh;
        float w0 = Ug[(2 * kp) * UDIM + col];
        float w1 = Ug[(2 * kp + 1) * UDIM + col];
        uint32_t hi, lo;
        split2(w0, w1, hi, lo);
        int nf48 = n >> 3, nn = n & 7, ks = kp >> 3, chi = (kp >> 2) & 1;
        uint32_t off = ((uint32_t)(nf48 * 8 + ks) << 8) + ((nn * 4 + (kp & 3)) << 3) + (chi << 2);
        sts32(sb + OFF2_BLO + off, hi);
    }
    __syncthreads();

    // each warp loads its resident B-hi fragments (64 regs)
    uint32_t bhi[4][8][2];
    #pragma unroll
    for (int nf = 0; nf < 4; nf++)
        #pragma unroll
        for (int ks = 0; ks < 8; ks++)
            lds64(bhi[nf][ks],
                  sb + OFF2_BLO + (((uint32_t)((wid * 4 + nf) * 8 + ks)) << 8) + (lane << 3));
    __syncthreads();

    // ---- overwrite B region with lo parts ----
    for (int idx = tid; idx < 384 * 64; idx += 384) {
        int n = idx >> 6, kp = idx & 63;
        int g = n >> 7, col = n & 127;
        const float* Ug = (g == 0) ? Ur : (g == 1) ? Uz : Uh;
        float w0 = Ug[(2 * kp) * UDIM + col];
        float w1 = Ug[(2 * kp + 1) * UDIM + col];
        uint32_t hi, lo;
        split2(w0, w1, hi, lo);
        int nf48 = n >> 3, nn = n & 7, ks = kp >> 3, chi = (kp >> 2) & 1;
        uint32_t off = ((uint32_t)(nf48 * 8 + ks) << 8) + ((nn * 4 + (kp & 3)) << 3) + (chi << 2);
        sts32(sb + OFF2_BLO + off, lo);
    }
    // ---- initial A-frag from h0 ----
    for (int p = tid; p < cnt * 64; p += 384) {
        int r = p >> 6, u2 = (p & 63) << 1;
        uint32_t hi, lo;
        split2(hs[r * UDIM + u2], hs[r * UDIM + u2 + 1], hi, lo);
        uint32_t o = afrag_off(r, u2);
        sts32(sb + OFF2_AFH + o, hi);
        sts32(sb + OFF2_AFL + o, lo);
    }
    __syncthreads();

    const int gate = wid >> 2;
    const int colb = ((wid & 3) << 5) + ((lane & 3) << 1);
    const int r1   = lane >> 2;

    for (int t = 0; t < TSTEPS; t++) {
        // ---- prefetch this step's pointwise operands ----
        {
            int nchunks = cnt * 96;
            for (int i = tid; i < nchunks; i += 384) {
                int rr = i / 96, q = i - rr * 96;
                size_t base = (size_t)(row0 + rr) * TSTEPS + t;
                cpa16(sb + OFF2_GXS + (uint32_t)(rr * GSTRIDE + q * 4) * 4,
                      g_G + base * GSTRIDE + q * 4);
            }
            if (tid < cnt) {
                size_t base = (size_t)(row0 + tid) * TSTEPS + t;
                cpa4(sb + OFF2_AS + tid * 4, inp + base * INSTRIDE + UDIM);
            }
            cpa_commit();
        }

        // ---- MMA phase: acc[16 x 32cols] = h @ U (3-pass split) ----
        float acc[4][4];
        #pragma unroll
        for (int nf = 0; nf < 4; nf++)
            #pragma unroll
            for (int q = 0; q < 4; q++) acc[nf][q] = 0.0f;

        #pragma unroll
        for (int ks = 0; ks < 8; ks++) {
            uint32_t Ah[4], Al[4];
            lds128(Ah, sb + OFF2_AFH + ks * 512 + lane * 16);
            lds128(Al, sb + OFF2_AFL + ks * 512 + lane * 16);
            #pragma unroll
            for (int nf = 0; nf < 4; nf++) {
                uint32_t Bl[2];
                lds64(Bl, sb + OFF2_BLO + (((uint32_t)((wid * 4 + nf) * 8 + ks)) << 8) + (lane << 3));
                mma16816(acc[nf], Ah, bhi[nf][ks]);
                mma16816(acc[nf], Ah, Bl);
                mma16816(acc[nf], Al, bhi[nf][ks]);
            }
        }

        // ---- scatter accs to smem (padded stride 132 avoids conflicts) ----
        #pragma unroll
        for (int nf = 0; nf < 4; nf++) {
            int colg = colb + (nf << 3);
            sts64f(sb + OFF2_ACC + (uint32_t)((gate * 16 + r1) * 132 + colg) * 4,
                   acc[nf][0], acc[nf][1]);
            sts64f(sb + OFF2_ACC + (uint32_t)((gate * 16 + r1 + 8) * 132 + colg) * 4,
                   acc[nf][2], acc[nf][3]);
        }
        cpa_wait0();
        __syncthreads();

        // ---- pointwise GRU update; writes out, hs, next A-frag ----
        for (int p = tid; p < cnt * 64; p += 384) {
            int r = p >> 6, u2 = (p & 63) << 1;
            size_t base = (size_t)(row0 + r) * TSTEPS + t;
            float2 xr = *(float2*)(gxs + r * GSTRIDE + u2);
            float2 xz = *(float2*)(gxs + r * GSTRIDE + UDIM + u2);
            float2 xh = *(float2*)(gxs + r * GSTRIDE + 2 * UDIM + u2);
            float  a  = as_s[r];
            float2 hp = *(float2*)(hs + r * UDIM + u2);

            float ar0 = accs[(r)      * 132 + u2], ar1 = accs[(r)      * 132 + u2 + 1];
            float az0 = accs[(16 + r) * 132 + u2], az1 = accs[(16 + r) * 132 + u2 + 1];
            float ah0 = accs[(32 + r) * 132 + u2], ah1 = accs[(32 + r) * 132 + u2 + 1];

            float rv0 = sigf(xr.x + ar0), rv1 = sigf(xr.y + ar1);
            float zv0 = sigf(xz.x + az0), zv1 = sigf(xz.y + az1);
            float ht0 = tanhfast(xh.x + rv0 * ah0);
            float ht1 = tanhfast(xh.y + rv1 * ah1);
            float u0 = a * zv0, u1 = a * zv1;
            float hn0 = (1.0f - u0) * hp.x + u0 * ht0;
            float hn1 = (1.0f - u1) * hp.y + u1 * ht1;

            *(float2*)(out + base * UDIM + u2) = make_float2(hn0, hn1);
            *(float2*)(hs + r * UDIM + u2)     = make_float2(hn0, hn1);

            uint32_t hi, lo;
            split2(hn0, hn1, hi, lo);
            uint32_t o = afrag_off(r, u2);
            sts32(sb + OFF2_AFH + o, hi);
            sts32(sb + OFF2_AFL + o, lo);
        }
        __syncthreads();
    }
}

// =====================================================================
// Launch
// Inputs (metadata order): inputs, h0, W_r, U_r, b_r, W_z, U_z, b_z, W_h, U_h, b_h
// =====================================================================
extern "C" void kernel_launch(void* const* d_in, const int* in_sizes, int n_in,
                              void* d_out, int out_size)
{
    const float* inp = (const float*)d_in[0];
    const float* h0  = (const float*)d_in[1];
    const float* Wr  = (const float*)d_in[2];
    const float* Ur  = (const float*)d_in[3];
    const float* br  = (const float*)d_in[4];
    const float* Wz  = (const float*)d_in[5];
    const float* Uz  = (const float*)d_in[6];
    const float* bz  = (const float*)d_in[7];
    const float* Wh  = (const float*)d_in[8];
    const float* Uh  = (const float*)d_in[9];
    const float* bh  = (const float*)d_in[10];
    float* out = (float*)d_out;

    cudaFuncSetAttribute(gemm_tc, cudaFuncAttributeMaxDynamicSharedMemorySize, GM_SMEM);
    cudaFuncSetAttribute(gru_recur, cudaFuncAttributeMaxDynamicSharedMemorySize, SMEM2);

    gemm_tc<<<148, 256, GM_SMEM>>>(inp, Wr, Wz, Wh, br, bz, bh);
    gru_recur<<<148, 384, SMEM2>>>(inp, h0, Ur, Uz, Uh, out);
}

// round 6
// speedup vs baseline: 3.3270x; 1.2008x over previous
#include <cuda_runtime.h>
#include <cuda_bf16.h>
#include <cstdint>

// Problem constants
#define TSTEPS   200
#define UDIM     128
#define BATCH    2048
#define MROWS    (BATCH * TSTEPS)     // 409600
#define GSTRIDE  384                  // xr|xz|xh concatenated
#define INSTRIDE 129                  // inputs last dim = U+1

// Scratch for precomputed input projections: 409600 x 384 fp32 = 629 MB
__device__ float g_G[157286400];      // MROWS * GSTRIDE

typedef unsigned long long ull;

// ---------------- fast activations ----------------
__device__ __forceinline__ float sigf(float x) {
    return __fdividef(1.0f, 1.0f + __expf(-x));
}
__device__ __forceinline__ float tanhfast(float x) {
    float e = __expf(-2.0f * fabsf(x));
    float t = __fdividef(1.0f - e, 1.0f + e);
    return copysignf(t, x);
}

// ---------------- cp.async helpers ----------------
__device__ __forceinline__ void cpa16(uint32_t saddr, const void* g) {
    asm volatile("cp.async.ca.shared.global [%0], [%1], 16;" :: "r"(saddr), "l"(g));
}
__device__ __forceinline__ void cpa4(uint32_t saddr, const void* g) {
    asm volatile("cp.async.ca.shared.global [%0], [%1], 4;" :: "r"(saddr), "l"(g));
}
__device__ __forceinline__ void cpa_commit() { asm volatile("cp.async.commit_group;"); }
__device__ __forceinline__ void cpa_wait0()  { asm volatile("cp.async.wait_group 0;"); }

// ---------------- mma.sync helpers ----------------
__device__ __forceinline__ void mma16816(float* c, const uint32_t* a, const uint32_t* b) {
    asm volatile(
        "mma.sync.aligned.m16n8k16.row.col.f32.bf16.bf16.f32 "
        "{%0,%1,%2,%3}, {%4,%5,%6,%7}, {%8,%9}, {%0,%1,%2,%3};"
        : "+f"(c[0]), "+f"(c[1]), "+f"(c[2]), "+f"(c[3])
        : "r"(a[0]), "r"(a[1]), "r"(a[2]), "r"(a[3]), "r"(b[0]), "r"(b[1]));
}
__device__ __forceinline__ void lds128(uint32_t* r, uint32_t addr) {
    asm volatile("ld.shared.v4.u32 {%0,%1,%2,%3}, [%4];"
        : "=r"(r[0]), "=r"(r[1]), "=r"(r[2]), "=r"(r[3]) : "r"(addr));
}
__device__ __forceinline__ void lds64(uint32_t* r, uint32_t addr) {
    asm volatile("ld.shared.v2.u32 {%0,%1}, [%2];"
        : "=r"(r[0]), "=r"(r[1]) : "r"(addr));
}
__device__ __forceinline__ void sts32(uint32_t addr, uint32_t v) {
    asm volatile("st.shared.u32 [%0], %1;" :: "r"(addr), "r"(v));
}
__device__ __forceinline__ void sts64f(uint32_t addr, float x, float y) {
    asm volatile("st.shared.v2.f32 [%0], {%1,%2};" :: "r"(addr), "f"(x), "f"(y));
}
// Split packed pair (x0, x1) into bf16x2 hi and lo parts. lo half of reg = x0.
__device__ __forceinline__ void split2(float x0, float x1, uint32_t& hi, uint32_t& lo) {
    asm("cvt.rn.bf16x2.f32 %0, %1, %2;" : "=r"(hi) : "f"(x1), "f"(x0));
    float h0 = __uint_as_float(hi << 16);
    float h1 = __uint_as_float(hi & 0xFFFF0000u);
    float l0 = x0 - h0;
    float l1 = x1 - h1;
    asm("cvt.rn.bf16x2.f32 %0, %1, %2;" : "=r"(lo) : "f"(l1), "f"(l0));
}

// =====================================================================
// Stage 1: G[m][n] = X[m][:] . Wcat[:][n] + bias, via mma.sync bf16
// 3-pass split. M-tile 128, N-tile 128 (one gate), K=128.
// NEW: cp.async pipeline — next tile's raw X staged into smem during the
// current tile's HMMA mainloop; convert phase reads smem, not DRAM.
// =====================================================================
#define OFF_AHI  0
#define OFF_ALO  32768
#define OFF_BHI  65536
#define OFF_BLO  98304
#define OFF_BIAS 131072
#define OFF_RAW  131584
#define GM_SMEM  (OFF_RAW + 65536)    // 197120 bytes

__global__ void __launch_bounds__(256, 1) gemm_tc(
    const float* __restrict__ inp,
    const float* __restrict__ Wr, const float* __restrict__ Wz, const float* __restrict__ Wh,
    const float* __restrict__ br, const float* __restrict__ bz, const float* __restrict__ bh)
{
    extern __shared__ __align__(16) char smem[];
    const uint32_t sb = (uint32_t)__cvta_generic_to_shared(smem);
    float* bias_s = (float*)(smem + OFF_BIAS);
    const float* raws = (const float*)(smem + OFF_RAW);

    const int tid  = threadIdx.x;
    const int wid  = tid >> 5;
    const int lane = tid & 31;
    const int wm   = wid >> 1;
    const int wn   = wid & 1;

    const int bid   = blockIdx.x;
    const int nblk  = bid % 3;
    const int start = bid / 3;
    const int mstride = (nblk == 0) ? 50 : 49;

    const float* Wg   = (nblk == 0) ? Wr : (nblk == 1) ? Wz : Wh;
    const float* bsrc = (nblk == 0) ? br : (nblk == 1) ? bz : bh;

    // ---- load + split W into B-fragment layout (once per CTA) ----
    {
        const int rbase = tid >> 6;
        const int kp    = tid & 63;
        const int ks  = kp >> 3;
        const int chi = (kp >> 2) & 1;
        #pragma unroll 4
        for (int j = 0; j < 32; j++) {
            int n = j * 4 + rbase;
            float w0 = Wg[(2 * kp) * UDIM + n];
            float w1 = Wg[(2 * kp + 1) * UDIM + n];
            uint32_t hi, lo;
            split2(w0, w1, hi, lo);
            int nfrag = n >> 3, nn = n & 7;
            uint32_t off = (uint32_t)((nfrag * 8 + ks) << 8) + ((nn * 4 + (kp & 3)) << 3) + (chi << 2);
            sts32(sb + OFF_BHI + off, hi);
            sts32(sb + OFF_BLO + off, lo);
        }
        if (tid < 128) bias_s[tid] = bsrc[tid];
    }

    // ---- prologue: prefetch first tile's raw X ----
    if (start < 3200) {
        const size_t m0 = (size_t)start * 128;
        #pragma unroll 8
        for (int j = 0; j < 64; j++) {
            int idx = j * 256 + tid;
            int row = idx >> 7, col = idx & 127;
            cpa4(sb + OFF_RAW + (uint32_t)idx * 4,
                 inp + (m0 + row) * INSTRIDE + col);
        }
    }
    cpa_commit();

    const int eg  = lane >> 2;
    const int et2 = (lane & 3) * 2;

    for (int mt = start; mt < 3200; mt += mstride) {
        const size_t m0 = (size_t)mt * 128;

        cpa_wait0();
        __syncthreads();

        // ---- convert raw X (smem) into A-fragment layout ----
        {
            const int rbase = tid >> 6;
            const int kp    = tid & 63;
            const int ks  = kp >> 3;
            const int t   = kp & 3;
            const int chi = (kp >> 2) & 1;
            #pragma unroll 4
            for (int j = 0; j < 32; j++) {
                int m = j * 4 + rbase;
                float2 x = *(const float2*)(raws + m * 128 + 2 * kp);
                uint32_t hi, lo;
                split2(x.x, x.y, hi, lo);
                int mfrag = m >> 4, r = m & 15, g = r & 7, rh = r >> 3;
                int lane_sw = (g * 4 + t) ^ ((ks & 3) << 1);
                uint32_t off = (uint32_t)((mfrag * 8 + ks) << 9) + (lane_sw << 4) + ((chi * 2 + rh) << 2);
                sts32(sb + OFF_AHI + off, hi);
                sts32(sb + OFF_ALO + off, lo);
            }
        }
        __syncthreads();

        // ---- prefetch next tile's raw X (overlaps mainloop) ----
        {
            int nmt = mt + mstride;
            if (nmt < 3200) {
                const size_t nm0 = (size_t)nmt * 128;
                #pragma unroll 8
                for (int j = 0; j < 64; j++) {
                    int idx = j * 256 + tid;
                    int row = idx >> 7, col = idx & 127;
                    cpa4(sb + OFF_RAW + (uint32_t)idx * 4,
                         inp + (nm0 + row) * INSTRIDE + col);
                }
            }
            cpa_commit();
        }

        // ---- mma mainloop ----
        float acc[2][8][4];
        #pragma unroll
        for (int mf = 0; mf < 2; mf++)
            #pragma unroll
            for (int nf = 0; nf < 8; nf++)
                #pragma unroll
                for (int q = 0; q < 4; q++) acc[mf][nf][q] = 0.0f;

        #pragma unroll 2
        for (int ks = 0; ks < 8; ks++) {
            const uint32_t asw = (uint32_t)((lane ^ ((ks & 3) << 1)) << 4);
            uint32_t Ahi[2][4], Alo[2][4];
            #pragma unroll
            for (int mf = 0; mf < 2; mf++) {
                uint32_t blk = (uint32_t)(((wm * 2 + mf) * 8 + ks) << 9) + asw;
                lds128(Ahi[mf], sb + OFF_AHI + blk);
                lds128(Alo[mf], sb + OFF_ALO + blk);
            }
            uint32_t Bhi[8][2], Blo[8][2];
            #pragma unroll
            for (int nf = 0; nf < 8; nf++) {
                uint32_t blk = (uint32_t)(((wn * 8 + nf) * 8 + ks) << 8) + (lane << 3);
                lds64(Bhi[nf], sb + OFF_BHI + blk);
                lds64(Blo[nf], sb + OFF_BLO + blk);
            }
            #pragma unroll
            for (int mf = 0; mf < 2; mf++)
                #pragma unroll
                for (int nf = 0; nf < 8; nf++) {
                    mma16816(acc[mf][nf], Ahi[mf], Bhi[nf]);
                    mma16816(acc[mf][nf], Ahi[mf], Blo[nf]);
                    mma16816(acc[mf][nf], Alo[mf], Bhi[nf]);
                }
        }

        // ---- epilogue: direct STG.64 ----
        #pragma unroll
        for (int mf = 0; mf < 2; mf++) {
            size_t row = m0 + wm * 32 + mf * 16 + eg;
            #pragma unroll
            for (int nf = 0; nf < 8; nf++) {
                int coll = wn * 64 + nf * 8 + et2;
                float b0 = bias_s[coll], b1 = bias_s[coll + 1];
                float* gp = g_G + row * GSTRIDE + nblk * 128 + coll;
                float2 v0 = make_float2(acc[mf][nf][0] + b0, acc[mf][nf][1] + b1);
                float2 v1 = make_float2(acc[mf][nf][2] + b0, acc[mf][nf][3] + b1);
                *(float2*)gp = v0;
                *(float2*)(gp + 8 * GSTRIDE) = v1;
            }
        }
    }
}

// =====================================================================
// Stage 2: tensor-core recurrence (unchanged from round 5).
// =====================================================================
#define OFF2_BLO  0                    // 48 nfrags x 8 ks x 256B = 98304
#define OFF2_AFH  98304                // 8 ks x 32 lanes x 16B = 4096
#define OFF2_AFL  102400               // 4096
#define OFF2_ACC  106496               // 3*16*132*4 = 25344
#define OFF2_HS   131840               // 16*128*4 = 8192
#define OFF2_GXS  140032               // 14*384*4 = 21504
#define OFF2_AS   161536               // 64
#define SMEM2     161600

__device__ __forceinline__ uint32_t afrag_off(int r, int u2) {
    int ks   = u2 >> 4;
    int lane = ((r & 7) << 2) | ((u2 >> 1) & 3);
    int reg  = (r >> 3) | (((u2 >> 3) & 1) << 1);
    return (uint32_t)(ks * 512 + lane * 16 + reg * 4);
}

__global__ void __launch_bounds__(384, 1) gru_recur(
    const float* __restrict__ inp,
    const float* __restrict__ h0,
    const float* __restrict__ Ur, const float* __restrict__ Uz, const float* __restrict__ Uh,
    float* __restrict__ out)
{
    extern __shared__ __align__(16) char smem2[];
    const uint32_t sb = (uint32_t)__cvta_generic_to_shared(smem2);
    float* hs   = (float*)(smem2 + OFF2_HS);
    float* gxs  = (float*)(smem2 + OFF2_GXS);
    float* as_s = (float*)(smem2 + OFF2_AS);
    float* accs = (float*)(smem2 + OFF2_ACC);

    const int tid  = threadIdx.x;
    const int wid  = tid >> 5;
    const int lane = tid & 31;

    // Balanced row partition over 148 CTAs: 124x14 + 24x13 = 2048
    const int bid = blockIdx.x;
    int row0, cnt;
    if (bid < 124) { row0 = bid * 14;                    cnt = 14; }
    else           { row0 = 124 * 14 + (bid - 124) * 13; cnt = 13; }

    // zero A-frag regions (covers padded rows cnt..15 forever)
    for (int i = tid; i < 1024; i += 384) {
        ((uint32_t*)(smem2 + OFF2_AFH))[i] = 0;
        ((uint32_t*)(smem2 + OFF2_AFL))[i] = 0;
    }
    // load h0
    for (int i = tid; i < cnt * UDIM; i += 384)
        hs[i] = h0[(size_t)row0 * UDIM + i];

    // ---- build B (U-cat) hi parts in frag layout ----
    for (int idx = tid; idx < 384 * 64; idx += 384) {
        int n = idx >> 6, kp = idx & 63;
        int g = n >> 7, col = n & 127;
        const float* Ug = (g == 0) ? Ur : (g == 1) ? Uz : Uh;
        float w0 = Ug[(2 * kp) * UDIM + col];
        float w1 = Ug[(2 * kp + 1) * UDIM + col];
        uint32_t hi, lo;
        split2(w0, w1, hi, lo);
        int nf48 = n >> 3, nn = n & 7, ks = kp >> 3, chi = (kp >> 2) & 1;
        uint32_t off = ((uint32_t)(nf48 * 8 + ks) << 8) + ((nn * 4 + (kp & 3)) << 3) + (chi << 2);
        sts32(sb + OFF2_BLO + off, hi);
    }
    __syncthreads();

    // each warp loads its resident B-hi fragments (64 regs)
    uint32_t bhi[4][8][2];
    #pragma unroll
    for (int nf = 0; nf < 4; nf++)
        #pragma unroll
        for (int ks = 0; ks < 8; ks++)
            lds64(bhi[nf][ks],
                  sb + OFF2_BLO + (((uint32_t)((wid * 4 + nf) * 8 + ks)) << 8) + (lane << 3));
    __syncthreads();

    // ---- overwrite B region with lo parts ----
    for (int idx = tid; idx < 384 * 64; idx += 384) {
        int n = idx >> 6, kp = idx & 63;
        int g = n >> 7, col = n & 127;
        const float* Ug = (g == 0) ? Ur : (g == 1) ? Uz : Uh;
        float w0 = Ug[(2 * kp) * UDIM + col];
        float w1 = Ug[(2 * kp + 1) * UDIM + col];
        uint32_t hi, lo;
        split2(w0, w1, hi, lo);
        int nf48 = n >> 3, nn = n & 7, ks = kp >> 3, chi = (kp >> 2) & 1;
        uint32_t off = ((uint32_t)(nf48 * 8 + ks) << 8) + ((nn * 4 + (kp & 3)) << 3) + (chi << 2);
        sts32(sb + OFF2_BLO + off, lo);
    }
    // ---- initial A-frag from h0 ----
    for (int p = tid; p < cnt * 64; p += 384) {
        int r = p >> 6, u2 = (p & 63) << 1;
        uint32_t hi, lo;
        split2(hs[r * UDIM + u2], hs[r * UDIM + u2 + 1], hi, lo);
        uint32_t o = afrag_off(r, u2);
        sts32(sb + OFF2_AFH + o, hi);
        sts32(sb + OFF2_AFL + o, lo);
    }
    __syncthreads();

    const int gate = wid >> 2;
    const int colb = ((wid & 3) << 5) + ((lane & 3) << 1);
    const int r1   = lane >> 2;

    for (int t = 0; t < TSTEPS; t++) {
        // ---- prefetch this step's pointwise operands ----
        {
            int nchunks = cnt * 96;
            for (int i = tid; i < nchunks; i += 384) {
                int rr = i / 96, q = i - rr * 96;
                size_t base = (size_t)(row0 + rr) * TSTEPS + t;
                cpa16(sb + OFF2_GXS + (uint32_t)(rr * GSTRIDE + q * 4) * 4,
                      g_G + base * GSTRIDE + q * 4);
            }
            if (tid < cnt) {
                size_t base = (size_t)(row0 + tid) * TSTEPS + t;
                cpa4(sb + OFF2_AS + tid * 4, inp + base * INSTRIDE + UDIM);
            }
            cpa_commit();
        }

        // ---- MMA phase: acc[16 x 32cols] = h @ U (3-pass split) ----
        float acc[4][4];
        #pragma unroll
        for (int nf = 0; nf < 4; nf++)
            #pragma unroll
            for (int q = 0; q < 4; q++) acc[nf][q] = 0.0f;

        #pragma unroll
        for (int ks = 0; ks < 8; ks++) {
            uint32_t Ah[4], Al[4];
            lds128(Ah, sb + OFF2_AFH + ks * 512 + lane * 16);
            lds128(Al, sb + OFF2_AFL + ks * 512 + lane * 16);
            #pragma unroll
            for (int nf = 0; nf < 4; nf++) {
                uint32_t Bl[2];
                lds64(Bl, sb + OFF2_BLO + (((uint32_t)((wid * 4 + nf) * 8 + ks)) << 8) + (lane << 3));
                mma16816(acc[nf], Ah, bhi[nf][ks]);
                mma16816(acc[nf], Ah, Bl);
                mma16816(acc[nf], Al, bhi[nf][ks]);
            }
        }

        // ---- scatter accs to smem (padded stride 132) ----
        #pragma unroll
        for (int nf = 0; nf < 4; nf++) {
            int colg = colb + (nf << 3);
            sts64f(sb + OFF2_ACC + (uint32_t)((gate * 16 + r1) * 132 + colg) * 4,
                   acc[nf][0], acc[nf][1]);
            sts64f(sb + OFF2_ACC + (uint32_t)((gate * 16 + r1 + 8) * 132 + colg) * 4,
                   acc[nf][2], acc[nf][3]);
        }
        cpa_wait0();
        __syncthreads();

        // ---- pointwise GRU update; writes out, hs, next A-frag ----
        for (int p = tid; p < cnt * 64; p += 384) {
            int r = p >> 6, u2 = (p & 63) << 1;
            size_t base = (size_t)(row0 + r) * TSTEPS + t;
            float2 xr = *(float2*)(gxs + r * GSTRIDE + u2);
            float2 xz = *(float2*)(gxs + r * GSTRIDE + UDIM + u2);
            float2 xh = *(float2*)(gxs + r * GSTRIDE + 2 * UDIM + u2);
            float  a  = as_s[r];
            float2 hp = *(float2*)(hs + r * UDIM + u2);

            float ar0 = accs[(r)      * 132 + u2], ar1 = accs[(r)      * 132 + u2 + 1];
            float az0 = accs[(16 + r) * 132 + u2], az1 = accs[(16 + r) * 132 + u2 + 1];
            float ah0 = accs[(32 + r) * 132 + u2], ah1 = accs[(32 + r) * 132 + u2 + 1];

            float rv0 = sigf(xr.x + ar0), rv1 = sigf(xr.y + ar1);
            float zv0 = sigf(xz.x + az0), zv1 = sigf(xz.y + az1);
            float ht0 = tanhfast(xh.x + rv0 * ah0);
            float ht1 = tanhfast(xh.y + rv1 * ah1);
            float u0 = a * zv0, u1 = a * zv1;
            float hn0 = (1.0f - u0) * hp.x + u0 * ht0;
            float hn1 = (1.0f - u1) * hp.y + u1 * ht1;

            *(float2*)(out + base * UDIM + u2) = make_float2(hn0, hn1);
            *(float2*)(hs + r * UDIM + u2)     = make_float2(hn0, hn1);

            uint32_t hi, lo;
            split2(hn0, hn1, hi, lo);
            uint32_t o = afrag_off(r, u2);
            sts32(sb + OFF2_AFH + o, hi);
            sts32(sb + OFF2_AFL + o, lo);
        }
        __syncthreads();
    }
}

// =====================================================================
// Launch
// Inputs (metadata order): inputs, h0, W_r, U_r, b_r, W_z, U_z, b_z, W_h, U_h, b_h
// =====================================================================
extern "C" void kernel_launch(void* const* d_in, const int* in_sizes, int n_in,
                              void* d_out, int out_size)
{
    const float* inp = (const float*)d_in[0];
    const float* h0  = (const float*)d_in[1];
    const float* Wr  = (const float*)d_in[2];
    const float* Ur  = (const float*)d_in[3];
    const float* br  = (const float*)d_in[4];
    const float* Wz  = (const float*)d_in[5];
    const float* Uz  = (const float*)d_in[6];
    const float* bz  = (const float*)d_in[7];
    const float* Wh  = (const float*)d_in[8];
    const float* Uh  = (const float*)d_in[9];
    const float* bh  = (const float*)d_in[10];
    float* out = (float*)d_out;

    cudaFuncSetAttribute(gemm_tc, cudaFuncAttributeMaxDynamicSharedMemorySize, GM_SMEM);
    cudaFuncSetAttribute(gru_recur, cudaFuncAttributeMaxDynamicSharedMemorySize, SMEM2);

    gemm_tc<<<148, 256, GM_SMEM>>>(inp, Wr, Wz, Wh, br, bz, bh);
    gru_recur<<<148, 384, SMEM2>>>(inp, h0, Ur, Uz, Uh, out);
}